// round 15
// baseline (speedup 1.0000x reference)
#include <cuda_runtime.h>
#include <cstdint>
typedef unsigned long long ULL;

__device__ float2 g_A[16*64*256*32];   // [bc][h][ky]
__device__ float2 g_X[16*32*32*64];    // [b][mode][c]
__device__ float2 g_M[16*64*32*32];    // [bo][kx][ky]
__device__ float2 g_T[16*64*256*32];   // [bo][h][ky]
__device__ float2 g_Wt[1024*64*64];    // [m][c][o]
__device__ ULL        g_t1[256];       // (cos, -sin)
__device__ ulonglong2 g_t2[256];       // ((c,c),(s,-s))
__device__ ulonglong2 g_t4[256];       // ((c,s),(-s,c))
__device__ ULL        g_t5[256];       // (cos, sin)

__device__ __forceinline__ ULL ff2(ULL a, ULL b, ULL c) {
    ULL d; asm("fma.rn.f32x2 %0, %1, %2, %3;" : "=l"(d) : "l"(a), "l"(b), "l"(c)); return d;
}
__device__ __forceinline__ ULL add2(ULL a, ULL b) {
    ULL d; asm("add.rn.f32x2 %0, %1, %2;" : "=l"(d) : "l"(a), "l"(b)); return d;
}
__device__ __forceinline__ ULL sub2(ULL a, ULL b) {
    ULL d; asm("sub.rn.f32x2 %0, %1, %2;" : "=l"(d) : "l"(a), "l"(b)); return d;
}
__device__ __forceinline__ ULL mul2(ULL a, ULL b) {
    ULL d; asm("mul.rn.f32x2 %0, %1, %2;" : "=l"(d) : "l"(a), "l"(b)); return d;
}
__device__ __forceinline__ ULL pack2(float x, float y) {
    ULL d; asm("mov.b64 %0, {%1, %2};" : "=l"(d) : "f"(x), "f"(y)); return d;
}
__device__ __forceinline__ float2 unpack2(ULL v) {
    float2 r; asm("mov.b64 {%0, %1}, %2;" : "=f"(r.x), "=f"(r.y) : "l"(v)); return r;
}

__global__ void k_tw() {
    int k = threadIdx.x;
    double a = 6.283185307179586476925286766559 * k / 256.0;
    float c = (float)cos(a), s = (float)sin(a);
    g_t1[k] = pack2(c, -s);
    g_t2[k] = make_ulonglong2(pack2(c, c), pack2(s, -s));
    g_t4[k] = make_ulonglong2(pack2(c, s), pack2(-s, c));
    g_t5[k] = pack2(c, s);
}
__global__ __launch_bounds__(256) void k_wt(const float* __restrict__ wr,
                                            const float* __restrict__ wi) {
    __shared__ float2 st[32][33];
    int co0 = blockIdx.x * 32, m0 = blockIdx.y * 32;
    for (int i = threadIdx.x; i < 1024; i += 256) {
        int lco = i >> 5, lm = i & 31;
        size_t src = (size_t)(co0 + lco) * 1024 + m0 + lm;
        st[lco][lm] = make_float2(wr[src], wi[src]);
    }
    __syncthreads();
    for (int i = threadIdx.x; i < 1024; i += 256) {
        int lm = i >> 5, lco = i & 31;
        g_Wt[(size_t)(m0 + lm) * 4096 + co0 + lco] = st[lco][lm];
    }
}

// ---------------------------------------------------------------------------
// K1: fwd W, quad fold {w,128-w,128+w,256-w} (unchanged from R14 / 446us).
// ---------------------------------------------------------------------------
__global__ __launch_bounds__(256) void k_fwdW(const float* __restrict__ x) {
    __shared__ __align__(16) char buf[128 * 17 * 8 * 2];
    __shared__ ULL st1[256];
    __shared__ float4 sSp[128];
    ULL* sE = reinterpret_cast<ULL*>(buf);
    ULL* sO = sE + 128 * 17;
    int bc = blockIdx.x, h0 = blockIdx.y * 128, tid = threadIdx.x;
    int lane = tid & 31, wrp = tid >> 5;
    if (tid < 256) st1[tid] = g_t1[tid];
    const float* xr = x + (size_t)bc * 65536 + (size_t)h0 * 256;
    for (int i = tid; i < 128; i += 256) {
        const float* row = xr + i * 256;
        sSp[i] = make_float4(row[0], row[64], row[128], row[192]);
    }
    int w3 = wrp & 3, par = wrp & 1;
    float c64 = (w3 == 0) ? 1.f : ((w3 == 2) ? -1.f : 0.f);
    float s64 = (w3 == 1) ? 1.f : ((w3 == 3) ? -1.f : 0.f);
    float sg1 = par ? -1.f : 1.f;
    int kyv[4];
    #pragma unroll
    for (int k = 0; k < 4; k++) kyv[k] = wrp + 8 * k;
    __syncthreads();
    ULL acc[4][4];
    #pragma unroll
    for (int j = 0; j < 4; j++) {
        float4 sp = sSp[lane + 32 * j];
        ULL a = pack2(sp.x + sg1 * sp.z + c64 * (sp.y + sp.w), -s64 * (sp.y - sp.w));
        #pragma unroll
        for (int k = 0; k < 4; k++) acc[k][j] = a;
    }
    const ULL* sD = par ? sO : sE;

    for (int ph = 0; ph < 4; ph++) {
        int wb = ph * 16 + 1, nw = (ph == 3) ? 15 : 16;
        __syncthreads();
        for (int i = tid; i < 2048; i += 256) {
            int h = i >> 4, wl = i & 15;
            if (wl < nw) {
                int w = wb + wl;
                const float* row = xr + h * 256;
                float xa = row[w], xb = row[256 - w], xm = row[128 - w], xp = row[128 + w];
                float ap = xa + xb, am = xa - xb, bp = xm + xp, bm = xp - xm;
                sE[h * 17 + wl] = pack2(ap + bp, am + bm);
                sO[h * 17 + wl] = pack2(ap - bp, am - bm);
            }
        }
        __syncthreads();
        int idx[4];
        #pragma unroll
        for (int k = 0; k < 4; k++) idx[k] = (kyv[k] * wb) & 255;
        #pragma unroll 4
        for (int wl = 0; wl < nw; wl++) {
            ULL d0 = sD[lane * 17 + wl];
            ULL d1 = sD[(lane + 32) * 17 + wl];
            ULL d2 = sD[(lane + 64) * 17 + wl];
            ULL d3 = sD[(lane + 96) * 17 + wl];
            #pragma unroll
            for (int k = 0; k < 4; k++) {
                ULL t = st1[idx[k]];
                acc[k][0] = ff2(d0, t, acc[k][0]);
                acc[k][1] = ff2(d1, t, acc[k][1]);
                acc[k][2] = ff2(d2, t, acc[k][2]);
                acc[k][3] = ff2(d3, t, acc[k][3]);
                idx[k] = (idx[k] + kyv[k]) & 255;
            }
        }
    }
    __syncthreads();
    ULL* sRes = reinterpret_cast<ULL*>(buf);
    ULL s2 = pack2(1.f / 256.f, 1.f / 256.f);
    #pragma unroll
    for (int k = 0; k < 4; k++)
        #pragma unroll
        for (int j = 0; j < 4; j++)
            sRes[(lane + 32 * j) * 33 + kyv[k]] = mul2(acc[k][j], s2);
    __syncthreads();
    ULL* Ao = reinterpret_cast<ULL*>(&g_A[(size_t)bc * 8192 + (size_t)h0 * 32]);
    for (int i = tid; i < 4096; i += 256)
        Ao[i] = sRes[(i >> 5) * 33 + (i & 31)];
}

// K2: fwd H, h-parity fold (unchanged).
__global__ __launch_bounds__(256) void k_fwdH() {
    __shared__ ULL sP[128 * 32], sQ[128 * 32];
    __shared__ ulonglong2 st2[256];
    int bc = blockIdx.x;
    const ULL* A = reinterpret_cast<const ULL*>(&g_A[(size_t)bc * 8192]);
    if (threadIdx.x < 256) st2[threadIdx.x] = g_t2[threadIdx.x];
    for (int i = threadIdx.x; i < 4096; i += 256) {
        ULL a = A[i], b = A[i + 4096];
        sP[i] = add2(a, b); sQ[i] = sub2(a, b);
    }
    __syncthreads();
    int lane = threadIdx.x & 31, wrp = threadIdx.x >> 5;
    int par = wrp & 1, base = par + 8 * (wrp >> 1);
    const ULL* sD = par ? sQ : sP;
    ULL acc[4]; int idx[4]; int kxv[4];
    #pragma unroll
    for (int t = 0; t < 4; t++) { acc[t] = 0; idx[t] = 0; kxv[t] = base + 2 * t; }
    #pragma unroll 4
    for (int h = 0; h < 128; h++) {
        ULL dv = sD[h * 32 + lane];
        float2 f = unpack2(dv);
        ULL dsn = pack2(f.y, f.x);
        #pragma unroll
        for (int t = 0; t < 4; t++) {
            ulonglong2 tw = st2[idx[t]];
            acc[t] = ff2(dv, tw.x, ff2(dsn, tw.y, acc[t]));
            idx[t] = (idx[t] + kxv[t]) & 255;
        }
    }
    int b = bc >> 6, c = bc & 63;
    #pragma unroll
    for (int t = 0; t < 4; t++)
        g_X[((size_t)b * 1024 + kxv[t] * 32 + lane) * 64 + c] = unpack2(acc[t]);
}

// K3: channel mix (unchanged).
__global__ __launch_bounds__(256) void k_mix() {
    int m = blockIdx.x;
    __shared__ float2 Ws[4096], Xs[1024];
    for (int i = threadIdx.x; i < 4096; i += 256)
        Ws[i] = g_Wt[(size_t)m * 4096 + i];
    for (int i = threadIdx.x; i < 1024; i += 256)
        Xs[i] = g_X[((size_t)(i >> 6) * 1024 + m) * 64 + (i & 63)];
    __syncthreads();
    #pragma unroll
    for (int k = 0; k < 4; k++) {
        int id = threadIdx.x + k * 256, b = id >> 6, o = id & 63;
        float ar = 0.f, ai = 0.f;
        #pragma unroll 8
        for (int c = 0; c < 64; c++) {
            float2 X = Xs[b * 64 + c], W = Ws[c * 64 + o];
            ar = fmaf(X.x, W.x, fmaf(-X.y, W.y, ar));
            ai = fmaf(X.x, W.y, fmaf( X.y, W.x, ai));
        }
        g_M[((size_t)b * 64 + o) * 1024 + m] = make_float2(ar, ai);
    }
}

// K4: inv H, kx-parity fold (unchanged).
__global__ __launch_bounds__(256) void k_invH() {
    __shared__ ULL Ms[1024];
    __shared__ ulonglong2 st4[256];
    int bo = blockIdx.x;
    const ULL* M = reinterpret_cast<const ULL*>(&g_M[(size_t)bo * 1024]);
    if (threadIdx.x < 256) st4[threadIdx.x] = g_t4[threadIdx.x];
    for (int i = threadIdx.x; i < 1024; i += 256) Ms[i] = M[i];
    __syncthreads();
    int lane = threadIdx.x & 31, wrp = threadIdx.x >> 5, hb = wrp * 16;
    ULL E[16], O[16]; int idx[16];
    #pragma unroll
    for (int j = 0; j < 16; j++) { E[j] = 0; O[j] = 0; idx[j] = 0; }
    #pragma unroll
    for (int kx = 0; kx < 32; kx++) {
        float2 f = unpack2(Ms[kx * 32 + lane]);
        ULL mrr = pack2(f.x, f.x), mii = pack2(f.y, f.y);
        #pragma unroll
        for (int j = 0; j < 16; j++) {
            ulonglong2 tw = st4[idx[j]];
            if (kx & 1) O[j] = ff2(mrr, tw.x, ff2(mii, tw.y, O[j]));
            else        E[j] = ff2(mrr, tw.x, ff2(mii, tw.y, E[j]));
            idx[j] = (idx[j] + hb + j) & 255;
        }
    }
    float sv = (lane == 0 ? 1.f : 2.f) / 256.f;
    ULL s2 = pack2(sv, sv);
    ULL* T = reinterpret_cast<ULL*>(&g_T[(size_t)bo * 8192]);
    #pragma unroll
    for (int j = 0; j < 16; j++) {
        T[(hb + j) * 32 + lane]       = mul2(add2(E[j], O[j]), s2);
        T[(hb + j + 128) * 32 + lane] = mul2(sub2(E[j], O[j]), s2);
    }
}

// ---------------------------------------------------------------------------
// K5: inv W fp32, quad output fold {w,128-w,128+w,256-w}. grid (1024 bo, 8 h-tiles
// of 32), blk 256: slot=tid&63 -> w (slot0 covers {0,64,128,192}); hg=tid>>6 -> 8 h.
// acc_p (ky-parity p) += (TR,TI)*(c,s); Ts loads warp-broadcast LDS.128.
// ---------------------------------------------------------------------------
__global__ __launch_bounds__(256) void k_invW(float* __restrict__ out) {
    __shared__ ULL Ts[32 * 32];
    __shared__ ULL st5[256];
    int bo = blockIdx.x, h0 = blockIdx.y * 32, tid = threadIdx.x;
    if (tid < 256) st5[tid] = g_t5[tid];
    const ULL* Tg = reinterpret_cast<const ULL*>(&g_T[((size_t)bo * 256 + h0) * 32]);
    for (int i = tid; i < 1024; i += 256) Ts[i] = Tg[i];
    __syncthreads();
    int slot = tid & 63, hg = tid >> 6, hb = hg * 8;
    int w = slot ? slot : 64;
    ULL accE[8] = {}, accO[8] = {};
    float ze[8] = {}, zo[8] = {};
    int idx = 0;
    #pragma unroll 4
    for (int ky = 0; ky < 32; ky += 2) {
        ULL te = st5[idx]; idx = (idx + w) & 255;
        ULL to = st5[idx]; idx = (idx + w) & 255;
        #pragma unroll
        for (int j = 0; j < 8; j++) {
            ulonglong2 dd = *reinterpret_cast<const ulonglong2*>(&Ts[(hb + j) * 32 + ky]);
            accE[j] = ff2(dd.x, te, accE[j]);
            accO[j] = ff2(dd.y, to, accO[j]);
            if (slot == 0) {
                ze[j] += unpack2(dd.x).x;
                zo[j] += unpack2(dd.y).x;
            }
        }
    }
    float* op = out + (size_t)bo * 65536 + (size_t)h0 * 256;
    #pragma unroll
    for (int j = 0; j < 8; j++) {
        int h = hb + j;
        float2 e = unpack2(accE[j]), o = unpack2(accO[j]);
        float Pe = e.x - e.y, Me = e.x + e.y;
        float Po = o.x - o.y, Mo = o.x + o.y;
        if (slot) {
            op[h * 256 + w]       = Pe + Po;
            op[h * 256 + 256 - w] = Me + Mo;
            op[h * 256 + 128 + w] = Pe - Po;
            op[h * 256 + 128 - w] = Me - Mo;
        } else {
            op[h * 256 + 64]  = Pe + Po;
            op[h * 256 + 192] = Me + Mo;
            op[h * 256]       = ze[j] + zo[j];
            op[h * 256 + 128] = ze[j] - zo[j];
        }
    }
}

extern "C" void kernel_launch(void* const* d_in, const int* in_sizes, int n_in,
                              void* d_out, int out_size) {
    (void)in_sizes; (void)n_in; (void)out_size;
    const float* x  = (const float*)d_in[0];
    const float* wr = (const float*)d_in[1];
    const float* wi = (const float*)d_in[2];
    float* out = (float*)d_out;

    k_tw  <<<1, 256>>>();
    k_wt  <<<dim3(128, 32), 256>>>(wr, wi);
    k_fwdW<<<dim3(1024, 2), 256>>>(x);
    k_fwdH<<<1024, 256>>>();
    k_mix <<<1024, 256>>>();
    k_invH<<<1024, 256>>>();
    k_invW<<<dim3(1024, 8), 256>>>(out);
}

// round 16
// speedup vs baseline: 1.1755x; 1.1755x over previous
#include <cuda_runtime.h>
#include <cuda_bf16.h>
#include <cstdint>
typedef unsigned long long ULL;

__device__ float2 g_A[16*64*256*32];   // [bc][h][ky]
__device__ float2 g_X[16*32*32*64];    // [b][mode][c]
__device__ float2 g_M[16*64*32*32];    // [bo][kx][ky]
__device__ float2 g_T[16*64*256*32];   // [bo][h][ky]
__device__ float2 g_Wt[1024*64*64];    // [m][c][o]
__device__ ULL        g_t1[256];       // (cos, -sin)
__device__ ulonglong2 g_t2[256];       // ((c,c),(s,-s))
__device__ ulonglong2 g_t4[256];       // ((c,s),(s,c))
__device__ __nv_bfloat16 g_B5h[256*64], g_B5l[256*64];  // [w][k] k<32:cos else -sin

__device__ __forceinline__ ULL ff2(ULL a, ULL b, ULL c) {
    ULL d; asm("fma.rn.f32x2 %0, %1, %2, %3;" : "=l"(d) : "l"(a), "l"(b), "l"(c)); return d;
}
__device__ __forceinline__ ULL add2(ULL a, ULL b) {
    ULL d; asm("add.rn.f32x2 %0, %1, %2;" : "=l"(d) : "l"(a), "l"(b)); return d;
}
__device__ __forceinline__ ULL sub2(ULL a, ULL b) {
    ULL d; asm("sub.rn.f32x2 %0, %1, %2;" : "=l"(d) : "l"(a), "l"(b)); return d;
}
__device__ __forceinline__ ULL mul2(ULL a, ULL b) {
    ULL d; asm("mul.rn.f32x2 %0, %1, %2;" : "=l"(d) : "l"(a), "l"(b)); return d;
}
__device__ __forceinline__ ULL pack2(float x, float y) {
    ULL d; asm("mov.b64 %0, {%1, %2};" : "=l"(d) : "f"(x), "f"(y)); return d;
}
__device__ __forceinline__ float2 unpack2(ULL v) {
    float2 r; asm("mov.b64 {%0, %1}, %2;" : "=f"(r.x), "=f"(r.y) : "l"(v)); return r;
}
__device__ __forceinline__ void mma_bf16(float d[4], uint32_t a0, uint32_t a1,
                                         uint32_t a2, uint32_t a3,
                                         uint32_t b0, uint32_t b1) {
    asm("mma.sync.aligned.m16n8k16.row.col.f32.bf16.bf16.f32 "
        "{%0,%1,%2,%3}, {%4,%5,%6,%7}, {%8,%9}, {%0,%1,%2,%3};"
        : "+f"(d[0]), "+f"(d[1]), "+f"(d[2]), "+f"(d[3])
        : "r"(a0), "r"(a1), "r"(a2), "r"(a3), "r"(b0), "r"(b1));
}

__global__ void k_tw() {
    int k = threadIdx.x;
    double a = 6.283185307179586476925286766559 * k / 256.0;
    float c = (float)cos(a), s = (float)sin(a);
    g_t1[k] = pack2(c, -s);
    g_t2[k] = make_ulonglong2(pack2(c, c), pack2(s, -s));
    g_t4[k] = make_ulonglong2(pack2(c, s), pack2(s, c));
}
__global__ void k_tw2() {
    int w = blockIdx.x, k = threadIdx.x;
    double a = 6.283185307179586476925286766559 * ((k & 31) * w) / 256.0;
    float v = (k < 32) ? (float)cos(a) : -(float)sin(a);
    __nv_bfloat16 hi = __float2bfloat16(v);
    g_B5h[w * 64 + k] = hi;
    g_B5l[w * 64 + k] = __float2bfloat16(v - __bfloat162float(hi));
}
__global__ __launch_bounds__(256) void k_wt(const float* __restrict__ wr,
                                            const float* __restrict__ wi) {
    __shared__ float2 st[32][33];
    int co0 = blockIdx.x * 32, m0 = blockIdx.y * 32;
    for (int i = threadIdx.x; i < 1024; i += 256) {
        int lco = i >> 5, lm = i & 31;
        size_t src = (size_t)(co0 + lco) * 1024 + m0 + lm;
        st[lco][lm] = make_float2(wr[src], wi[src]);
    }
    __syncthreads();
    for (int i = threadIdx.x; i < 1024; i += 256) {
        int lm = i >> 5, lco = i & 31;
        g_Wt[(size_t)(m0 + lm) * 4096 + co0 + lco] = st[lco][lm];
    }
}

// K1: fwd W, quad fold (unchanged from R14 / 446us).
__global__ __launch_bounds__(256) void k_fwdW(const float* __restrict__ x) {
    __shared__ __align__(16) char buf[128 * 17 * 8 * 2];
    __shared__ ULL st1[256];
    __shared__ float4 sSp[128];
    ULL* sE = reinterpret_cast<ULL*>(buf);
    ULL* sO = sE + 128 * 17;
    int bc = blockIdx.x, h0 = blockIdx.y * 128, tid = threadIdx.x;
    int lane = tid & 31, wrp = tid >> 5;
    if (tid < 256) st1[tid] = g_t1[tid];
    const float* xr = x + (size_t)bc * 65536 + (size_t)h0 * 256;
    for (int i = tid; i < 128; i += 256) {
        const float* row = xr + i * 256;
        sSp[i] = make_float4(row[0], row[64], row[128], row[192]);
    }
    int w3 = wrp & 3, par = wrp & 1;
    float c64 = (w3 == 0) ? 1.f : ((w3 == 2) ? -1.f : 0.f);
    float s64 = (w3 == 1) ? 1.f : ((w3 == 3) ? -1.f : 0.f);
    float sg1 = par ? -1.f : 1.f;
    int kyv[4];
    #pragma unroll
    for (int k = 0; k < 4; k++) kyv[k] = wrp + 8 * k;
    __syncthreads();
    ULL acc[4][4];
    #pragma unroll
    for (int j = 0; j < 4; j++) {
        float4 sp = sSp[lane + 32 * j];
        ULL a = pack2(sp.x + sg1 * sp.z + c64 * (sp.y + sp.w), -s64 * (sp.y - sp.w));
        #pragma unroll
        for (int k = 0; k < 4; k++) acc[k][j] = a;
    }
    const ULL* sD = par ? sO : sE;
    for (int ph = 0; ph < 4; ph++) {
        int wb = ph * 16 + 1, nw = (ph == 3) ? 15 : 16;
        __syncthreads();
        for (int i = tid; i < 2048; i += 256) {
            int h = i >> 4, wl = i & 15;
            if (wl < nw) {
                int w = wb + wl;
                const float* row = xr + h * 256;
                float xa = row[w], xb = row[256 - w], xm = row[128 - w], xp = row[128 + w];
                float ap = xa + xb, am = xa - xb, bp = xm + xp, bm = xp - xm;
                sE[h * 17 + wl] = pack2(ap + bp, am + bm);
                sO[h * 17 + wl] = pack2(ap - bp, am - bm);
            }
        }
        __syncthreads();
        int idx[4];
        #pragma unroll
        for (int k = 0; k < 4; k++) idx[k] = (kyv[k] * wb) & 255;
        #pragma unroll 4
        for (int wl = 0; wl < nw; wl++) {
            ULL d0 = sD[lane * 17 + wl];
            ULL d1 = sD[(lane + 32) * 17 + wl];
            ULL d2 = sD[(lane + 64) * 17 + wl];
            ULL d3 = sD[(lane + 96) * 17 + wl];
            #pragma unroll
            for (int k = 0; k < 4; k++) {
                ULL t = st1[idx[k]];
                acc[k][0] = ff2(d0, t, acc[k][0]);
                acc[k][1] = ff2(d1, t, acc[k][1]);
                acc[k][2] = ff2(d2, t, acc[k][2]);
                acc[k][3] = ff2(d3, t, acc[k][3]);
                idx[k] = (idx[k] + kyv[k]) & 255;
            }
        }
    }
    __syncthreads();
    ULL* sRes = reinterpret_cast<ULL*>(buf);
    ULL s2 = pack2(1.f / 256.f, 1.f / 256.f);
    #pragma unroll
    for (int k = 0; k < 4; k++)
        #pragma unroll
        for (int j = 0; j < 4; j++)
            sRes[(lane + 32 * j) * 33 + kyv[k]] = mul2(acc[k][j], s2);
    __syncthreads();
    ULL* Ao = reinterpret_cast<ULL*>(&g_A[(size_t)bc * 8192 + (size_t)h0 * 32]);
    for (int i = tid; i < 4096; i += 256)
        Ao[i] = sRes[(i >> 5) * 33 + (i & 31)];
}

// K2: fwd H, quad fold (kx-parity + (h,128-h)). 63-iter mainloop.
__global__ __launch_bounds__(256) void k_fwdH() {
    __shared__ ULL sGP[63 * 32], sKP[63 * 32], sGQ[63 * 32], sKQ[63 * 32];
    __shared__ ULL sD0[64], sD64[64];
    __shared__ ulonglong2 st2[256];
    int bc = blockIdx.x, tid = threadIdx.x;
    const float2* A = &g_A[(size_t)bc * 8192];
    if (tid < 256) st2[tid] = g_t2[tid];
    for (int i = tid; i < 2016; i += 256) {
        int ky = i & 31, h = (i >> 5) + 1;
        float2 a1 = A[h * 32 + ky],         a2 = A[(h + 128) * 32 + ky];
        float2 a3 = A[(128 - h) * 32 + ky], a4 = A[(256 - h) * 32 + ky];
        float Px = a1.x + a2.x, Py = a1.y + a2.y, Qx = a1.x - a2.x, Qy = a1.y - a2.y;
        float Rx = a3.x + a4.x, Ry = a3.y + a4.y, Sx = a3.x - a4.x, Sy = a3.y - a4.y;
        sGP[i] = pack2(Px + Rx, Py + Ry);
        sKP[i] = pack2(Py - Ry, Px - Rx);
        sGQ[i] = pack2(Qx - Sx, Qy - Sy);
        sKQ[i] = pack2(Qy + Sy, Qx + Sx);
    }
    if (tid < 64) {
        int pr = tid >> 5, ky = tid & 31;
        float2 a0 = A[ky], a128 = A[128 * 32 + ky];
        float2 a64 = A[64 * 32 + ky], a192 = A[192 * 32 + ky];
        sD0[tid]  = pr ? pack2(a0.x - a128.x, a0.y - a128.y)
                       : pack2(a0.x + a128.x, a0.y + a128.y);
        sD64[tid] = pr ? pack2(a64.x - a192.x, a64.y - a192.y)
                       : pack2(a64.x + a192.x, a64.y + a192.y);
    }
    __syncthreads();
    int lane = tid & 31, wrp = tid >> 5;
    int par = wrp & 1, base = par + 8 * (wrp >> 1);
    const ULL* sG = par ? sGQ : sGP;
    const ULL* sK = par ? sKQ : sKP;
    float2 d0 = unpack2(sD0[par * 32 + lane]);
    float2 d64 = unpack2(sD64[par * 32 + lane]);
    ULL acc[4]; int idx[4], kxv[4];
    #pragma unroll
    for (int t = 0; t < 4; t++) {
        kxv[t] = base + 2 * t;
        float sg = ((kxv[t] >> 1) & 1) ? -1.f : 1.f;
        acc[t] = par ? pack2(d0.x + sg * d64.y, d0.y - sg * d64.x)
                     : pack2(d0.x + sg * d64.x, d0.y + sg * d64.y);
        idx[t] = kxv[t];
    }
    #pragma unroll 7
    for (int h = 1; h < 64; h++) {
        ULL G = sG[(h - 1) * 32 + lane];
        ULL K = sK[(h - 1) * 32 + lane];
        #pragma unroll
        for (int t = 0; t < 4; t++) {
            ulonglong2 tw = st2[idx[t]];
            acc[t] = ff2(G, tw.x, ff2(K, tw.y, acc[t]));
            idx[t] = (idx[t] + kxv[t]) & 255;
        }
    }
    int b = bc >> 6, c = bc & 63;
    #pragma unroll
    for (int t = 0; t < 4; t++)
        g_X[((size_t)b * 1024 + kxv[t] * 32 + lane) * 64 + c] = unpack2(acc[t]);
}

// K3: channel mix (unchanged).
__global__ __launch_bounds__(256) void k_mix() {
    int m = blockIdx.x;
    __shared__ float2 Ws[4096], Xs[1024];
    for (int i = threadIdx.x; i < 4096; i += 256)
        Ws[i] = g_Wt[(size_t)m * 4096 + i];
    for (int i = threadIdx.x; i < 1024; i += 256)
        Xs[i] = g_X[((size_t)(i >> 6) * 1024 + m) * 64 + (i & 63)];
    __syncthreads();
    #pragma unroll
    for (int k = 0; k < 4; k++) {
        int id = threadIdx.x + k * 256, b = id >> 6, o = id & 63;
        float ar = 0.f, ai = 0.f;
        #pragma unroll 8
        for (int c = 0; c < 64; c++) {
            float2 X = Xs[b * 64 + c], W = Ws[c * 64 + o];
            ar = fmaf(X.x, W.x, fmaf(-X.y, W.y, ar));
            ai = fmaf(X.x, W.y, fmaf( X.y, W.x, ai));
        }
        g_M[((size_t)b * 64 + o) * 1024 + m] = make_float2(ar, ai);
    }
}

// K4: inv H, kx-parity + shared-product fold -> 4 outputs per inner product.
__global__ __launch_bounds__(256) void k_invH() {
    __shared__ ULL Ms[1024];
    __shared__ ulonglong2 st4[256];
    int bo = blockIdx.x, tid = threadIdx.x;
    const ULL* M = reinterpret_cast<const ULL*>(&g_M[(size_t)bo * 1024]);
    if (tid < 256) st4[tid] = g_t4[tid];
    for (int i = tid; i < 1024; i += 256) Ms[i] = M[i];
    __syncthreads();
    int lane = tid & 31, wrp = tid >> 5, hb = wrp * 8;
    ULL P1e[8] = {}, P2e[8] = {}, P1o[8] = {}, P2o[8] = {};
    int idx[8];
    #pragma unroll
    for (int j = 0; j < 8; j++) idx[j] = 0;
    #pragma unroll 4
    for (int kx = 0; kx < 32; kx += 2) {
        float2 f = unpack2(Ms[kx * 32 + lane]);
        ULL mrr = pack2(f.x, f.x), mii = pack2(f.y, f.y);
        #pragma unroll
        for (int j = 0; j < 8; j++) {
            ulonglong2 tw = st4[idx[j]];
            P1e[j] = ff2(mrr, tw.x, P1e[j]);
            P2e[j] = ff2(mii, tw.y, P2e[j]);
            idx[j] = (idx[j] + hb + j) & 255;
        }
        float2 g = unpack2(Ms[(kx + 1) * 32 + lane]);
        ULL nrr = pack2(g.x, g.x), nii = pack2(g.y, g.y);
        #pragma unroll
        for (int j = 0; j < 8; j++) {
            ulonglong2 tw = st4[idx[j]];
            P1o[j] = ff2(nrr, tw.x, P1o[j]);
            P2o[j] = ff2(nii, tw.y, P2o[j]);
            idx[j] = (idx[j] + hb + j) & 255;
        }
    }
    float s = (lane == 0 ? 1.f : 2.f) / 256.f;
    float2* T = &g_T[(size_t)bo * 8192];
    #pragma unroll
    for (int j = 0; j < 8; j++) {
        int h = hb + j;
        float2 e1 = unpack2(P1e[j]), e2 = unpack2(P2e[j]);
        float2 o1 = unpack2(P1o[j]), o2 = unpack2(P2o[j]);
        float Aex = e1.x - e2.x, Aey = e1.y + e2.y;
        float Bex = e1.x + e2.x, Bey = e2.y - e1.y;
        float Aox = o1.x - o2.x, Aoy = o1.y + o2.y;
        float Box = o1.x + o2.x, Boy = o2.y - o1.y;
        T[h * 32 + lane]                 = make_float2(s * (Aex + Aox), s * (Aey + Aoy));
        T[(h + 128) * 32 + lane]         = make_float2(s * (Aex - Aox), s * (Aey - Aoy));
        T[((128 - h) & 255) * 32 + lane] = make_float2(s * (Bex - Box), s * (Bey - Boy));
        T[((256 - h) & 255) * 32 + lane] = make_float2(s * (Bex + Box), s * (Bey + Boy));
    }
    if (wrp == 0) {      // T[64], T[192]
        float S0x = 0.f, S0y = 0.f, S1x = 0.f, S1y = 0.f;
        for (int kx = 0; kx < 32; kx++) {
            float2 f = unpack2(Ms[kx * 32 + lane]);
            int r = kx & 3;
            if (r == 0)      { S0x += f.x; S0y += f.y; }
            else if (r == 1) { S1x -= f.y; S1y += f.x; }
            else if (r == 2) { S0x -= f.x; S0y -= f.y; }
            else             { S1x += f.y; S1y -= f.x; }
        }
        T[64 * 32 + lane]  = make_float2(s * (S0x + S1x), s * (S0y + S1y));
        T[192 * 32 + lane] = make_float2(s * (S0x - S1x), s * (S0y - S1y));
    }
}

// K5: inverse W via mma.sync bf16 2-split (unchanged from R14).
__global__ __launch_bounds__(256) void k_invW(float* __restrict__ out) {
    __shared__ uint32_t As[2][64][32];
    __shared__ uint32_t Bs[2][128][32];
    int bog = blockIdx.x, w0 = blockIdx.y * 128, h0 = blockIdx.z * 64;
    int tid = threadIdx.x;
    for (int i = tid; i < 4096; i += 256) {
        int w = i >> 5, cb = i & 31;
        int sc = cb ^ ((w & 7) << 2);
        Bs[0][w][sc] = *reinterpret_cast<const uint32_t*>(&g_B5h[(w0 + w) * 64 + cb * 2]);
        Bs[1][w][sc] = *reinterpret_cast<const uint32_t*>(&g_B5l[(w0 + w) * 64 + cb * 2]);
    }
    int lane = tid & 31, wrp = tid >> 5;
    int gid = lane >> 2, tig = lane & 3;
    int wm = wrp & 1, wn = wrp >> 1;
    for (int s = 0; s < 4; s++) {
        int bo = bog * 4 + s;
        __syncthreads();
        const float2* T = &g_T[((size_t)bo * 256 + h0) * 32];
        __nv_bfloat16* Ab = reinterpret_cast<__nv_bfloat16*>(As);
        for (int i = tid; i < 2048; i += 256) {
            int h = i >> 5, ky = i & 31;
            float2 v = T[i];
            #pragma unroll
            for (int q = 0; q < 2; q++) {
                int k = ky + q * 32;
                float f = q ? v.y : v.x;
                __nv_bfloat16 hi = __float2bfloat16(f);
                __nv_bfloat16 lo = __float2bfloat16(f - __bfloat162float(hi));
                int wd = (k >> 1) ^ ((h & 7) << 2);
                int base = (h * 32 + wd) * 2 + (k & 1);
                Ab[base] = hi;
                Ab[4096 + base] = lo;
            }
        }
        __syncthreads();
        float d[2][4][4];
        #pragma unroll
        for (int mt = 0; mt < 2; mt++)
            #pragma unroll
            for (int nt = 0; nt < 4; nt++)
                { d[mt][nt][0]=0.f; d[mt][nt][1]=0.f; d[mt][nt][2]=0.f; d[mt][nt][3]=0.f; }
        #pragma unroll
        for (int c = 0; c < 12; c++) {
            int asel = (c >= 8) ? 1 : 0;
            int bsel = (c >= 4 && c < 8) ? 1 : 0;
            int kb = (c & 3) * 8;
            uint32_t a[2][4];
            #pragma unroll
            for (int mt = 0; mt < 2; mt++) {
                int r0 = wm * 32 + mt * 16 + gid, r1 = r0 + 8;
                a[mt][0] = As[asel][r0][(kb + tig)     ^ ((r0 & 7) << 2)];
                a[mt][1] = As[asel][r1][(kb + tig)     ^ ((r1 & 7) << 2)];
                a[mt][2] = As[asel][r0][(kb + 4 + tig) ^ ((r0 & 7) << 2)];
                a[mt][3] = As[asel][r1][(kb + 4 + tig) ^ ((r1 & 7) << 2)];
            }
            #pragma unroll
            for (int nt = 0; nt < 4; nt++) {
                int wr_ = wn * 32 + nt * 8 + gid;
                uint32_t b0 = Bs[bsel][wr_][(kb + tig)     ^ ((wr_ & 7) << 2)];
                uint32_t b1 = Bs[bsel][wr_][(kb + 4 + tig) ^ ((wr_ & 7) << 2)];
                #pragma unroll
                for (int mt = 0; mt < 2; mt++)
                    mma_bf16(d[mt][nt], a[mt][0], a[mt][1], a[mt][2], a[mt][3], b0, b1);
            }
        }
        float* op = out + (size_t)bo * 65536 + (size_t)h0 * 256 + w0;
        #pragma unroll
        for (int mt = 0; mt < 2; mt++) {
            int r0 = wm * 32 + mt * 16 + gid;
            #pragma unroll
            for (int nt = 0; nt < 4; nt++) {
                int cc = wn * 32 + nt * 8 + tig * 2;
                *reinterpret_cast<float2*>(op + (size_t)r0 * 256 + cc) =
                    make_float2(d[mt][nt][0], d[mt][nt][1]);
                *reinterpret_cast<float2*>(op + (size_t)(r0 + 8) * 256 + cc) =
                    make_float2(d[mt][nt][2], d[mt][nt][3]);
            }
        }
    }
}

extern "C" void kernel_launch(void* const* d_in, const int* in_sizes, int n_in,
                              void* d_out, int out_size) {
    (void)in_sizes; (void)n_in; (void)out_size;
    const float* x  = (const float*)d_in[0];
    const float* wr = (const float*)d_in[1];
    const float* wi = (const float*)d_in[2];
    float* out = (float*)d_out;

    k_tw  <<<1, 256>>>();
    k_tw2 <<<256, 64>>>();
    k_wt  <<<dim3(128, 32), 256>>>(wr, wi);
    k_fwdW<<<dim3(1024, 2), 256>>>(x);
    k_fwdH<<<1024, 256>>>();
    k_mix <<<1024, 256>>>();
    k_invH<<<1024, 256>>>();
    k_invW<<<dim3(256, 2, 4), 256>>>(out);
}

// round 17
// speedup vs baseline: 1.1943x; 1.0160x over previous
#include <cuda_runtime.h>
#include <cuda_bf16.h>
#include <cstdint>
typedef unsigned long long ULL;

__device__ float2 g_A[16*64*256*32];   // [bc][h][ky]
__device__ float2 g_X[16*32*32*64];    // [b][mode][c]
__device__ float2 g_M[16*64*32*32];    // [bo][kx][ky]
__device__ float2 g_T[16*64*256*32];   // [bo][h][ky]
__device__ float2 g_Wt[1024*64*64];    // [m][c][o]
__device__ ULL        g_t1[256];       // (cos, -sin)
__device__ ulonglong2 g_t2[256];       // ((c,c),(s,-s))
__device__ ulonglong2 g_t4[256];       // ((c,s),(s,c))
__device__ __nv_bfloat16 g_B5h[256*64], g_B5l[256*64];  // [w][k] k<32:cos else -sin

__device__ __forceinline__ ULL ff2(ULL a, ULL b, ULL c) {
    ULL d; asm("fma.rn.f32x2 %0, %1, %2, %3;" : "=l"(d) : "l"(a), "l"(b), "l"(c)); return d;
}
__device__ __forceinline__ ULL add2(ULL a, ULL b) {
    ULL d; asm("add.rn.f32x2 %0, %1, %2;" : "=l"(d) : "l"(a), "l"(b)); return d;
}
__device__ __forceinline__ ULL sub2(ULL a, ULL b) {
    ULL d; asm("sub.rn.f32x2 %0, %1, %2;" : "=l"(d) : "l"(a), "l"(b)); return d;
}
__device__ __forceinline__ ULL mul2(ULL a, ULL b) {
    ULL d; asm("mul.rn.f32x2 %0, %1, %2;" : "=l"(d) : "l"(a), "l"(b)); return d;
}
__device__ __forceinline__ ULL pack2(float x, float y) {
    ULL d; asm("mov.b64 %0, {%1, %2};" : "=l"(d) : "f"(x), "f"(y)); return d;
}
__device__ __forceinline__ float2 unpack2(ULL v) {
    float2 r; asm("mov.b64 {%0, %1}, %2;" : "=f"(r.x), "=f"(r.y) : "l"(v)); return r;
}
__device__ __forceinline__ void mma_bf16(float d[4], uint32_t a0, uint32_t a1,
                                         uint32_t a2, uint32_t a3,
                                         uint32_t b0, uint32_t b1) {
    asm("mma.sync.aligned.m16n8k16.row.col.f32.bf16.bf16.f32 "
        "{%0,%1,%2,%3}, {%4,%5,%6,%7}, {%8,%9}, {%0,%1,%2,%3};"
        : "+f"(d[0]), "+f"(d[1]), "+f"(d[2]), "+f"(d[3])
        : "r"(a0), "r"(a1), "r"(a2), "r"(a3), "r"(b0), "r"(b1));
}

__global__ void k_tw() {
    int k = threadIdx.x;
    double a = 6.283185307179586476925286766559 * k / 256.0;
    float c = (float)cos(a), s = (float)sin(a);
    g_t1[k] = pack2(c, -s);
    g_t2[k] = make_ulonglong2(pack2(c, c), pack2(s, -s));
    g_t4[k] = make_ulonglong2(pack2(c, s), pack2(s, c));
}
__global__ void k_tw2() {
    int w = blockIdx.x, k = threadIdx.x;
    double a = 6.283185307179586476925286766559 * ((k & 31) * w) / 256.0;
    float v = (k < 32) ? (float)cos(a) : -(float)sin(a);
    __nv_bfloat16 hi = __float2bfloat16(v);
    g_B5h[w * 64 + k] = hi;
    g_B5l[w * 64 + k] = __float2bfloat16(v - __bfloat162float(hi));
}
__global__ __launch_bounds__(256) void k_wt(const float* __restrict__ wr,
                                            const float* __restrict__ wi) {
    __shared__ float2 st[32][33];
    int co0 = blockIdx.x * 32, m0 = blockIdx.y * 32;
    for (int i = threadIdx.x; i < 1024; i += 256) {
        int lco = i >> 5, lm = i & 31;
        size_t src = (size_t)(co0 + lco) * 1024 + m0 + lm;
        st[lco][lm] = make_float2(wr[src], wi[src]);
    }
    __syncthreads();
    for (int i = threadIdx.x; i < 1024; i += 256) {
        int lm = i >> 5, lco = i & 31;
        g_Wt[(size_t)(m0 + lm) * 4096 + co0 + lco] = st[lco][lm];
    }
}

// ---------------------------------------------------------------------------
// K1: fwd W, quad fold + register-prefetch pipeline (global loads of phase p+1
// overlap compute of phase p). Single smem buffer; fold+store after post-compute
// sync. grid (1024 bc, 2 h-halves of 128), blk 256.
// ---------------------------------------------------------------------------
__global__ __launch_bounds__(256) void k_fwdW(const float* __restrict__ x) {
    __shared__ __align__(16) char buf[128 * 17 * 8 * 2];   // sE|sO (34.8KB), reused as sRes
    __shared__ ULL st1[256];
    __shared__ float4 sSp[128];
    ULL* sE = reinterpret_cast<ULL*>(buf);
    ULL* sO = sE + 128 * 17;
    int bc = blockIdx.x, h0 = blockIdx.y * 128, tid = threadIdx.x;
    int lane = tid & 31, wrp = tid >> 5;
    if (tid < 256) st1[tid] = g_t1[tid];
    const float* xr = x + (size_t)bc * 65536 + (size_t)h0 * 256;
    for (int i = tid; i < 128; i += 256) {
        const float* row = xr + i * 256;
        sSp[i] = make_float4(row[0], row[64], row[128], row[192]);
    }
    int w3 = wrp & 3, par = wrp & 1;
    float c64 = (w3 == 0) ? 1.f : ((w3 == 2) ? -1.f : 0.f);
    float s64 = (w3 == 1) ? 1.f : ((w3 == 3) ? -1.f : 0.f);
    float sg1 = par ? -1.f : 1.f;
    int kyv[4];
    #pragma unroll
    for (int k = 0; k < 4; k++) kyv[k] = wrp + 8 * k;

    // prefetch registers: 8 items x (xa, xb, xm, xp)
    float pa[8], pb[8], pm[8], pp[8];
    int ph_h[8], ph_wl[8];
    #pragma unroll
    for (int k = 0; k < 8; k++) {
        int i = tid + k * 256;
        ph_h[k] = i >> 4; ph_wl[k] = i & 15;
    }
    // prefetch phase 0 (w = wl+1, always < 64)
    #pragma unroll
    for (int k = 0; k < 8; k++) {
        int w = ph_wl[k] + 1;
        const float* row = xr + ph_h[k] * 256;
        pa[k] = row[w]; pb[k] = row[256 - w]; pm[k] = row[128 - w]; pp[k] = row[128 + w];
    }
    __syncthreads();

    ULL acc[4][4];
    #pragma unroll
    for (int j = 0; j < 4; j++) {
        float4 sp = sSp[lane + 32 * j];
        ULL a = pack2(sp.x + sg1 * sp.z + c64 * (sp.y + sp.w), -s64 * (sp.y - sp.w));
        #pragma unroll
        for (int k = 0; k < 4; k++) acc[k][j] = a;
    }
    const ULL* sD = par ? sO : sE;

    for (int ph = 0; ph < 4; ph++) {
        // fold + store current prefetch into smem
        int wb = ph * 16 + 1, nw = (ph == 3) ? 15 : 16;
        #pragma unroll
        for (int k = 0; k < 8; k++) {
            if (ph < 3 || ph_wl[k] < 15) {
                float ap = pa[k] + pb[k], am = pa[k] - pb[k];
                float bp = pm[k] + pp[k], bm = pp[k] - pm[k];
                sE[ph_h[k] * 17 + ph_wl[k]] = pack2(ap + bp, am + bm);
                sO[ph_h[k] * 17 + ph_wl[k]] = pack2(ap - bp, am - bm);
            }
        }
        __syncthreads();
        // prefetch next phase (global loads overlap the compute below)
        if (ph < 3) {
            #pragma unroll
            for (int k = 0; k < 8; k++) {
                int w = (ph + 1) * 16 + ph_wl[k] + 1;
                if (w < 64) {
                    const float* row = xr + ph_h[k] * 256;
                    pa[k] = row[w]; pb[k] = row[256 - w];
                    pm[k] = row[128 - w]; pp[k] = row[128 + w];
                }
            }
        }
        // compute current phase
        int idx[4];
        #pragma unroll
        for (int k = 0; k < 4; k++) idx[k] = (kyv[k] * wb) & 255;
        #pragma unroll 4
        for (int wl = 0; wl < nw; wl++) {
            ULL d0 = sD[lane * 17 + wl];
            ULL d1 = sD[(lane + 32) * 17 + wl];
            ULL d2 = sD[(lane + 64) * 17 + wl];
            ULL d3 = sD[(lane + 96) * 17 + wl];
            #pragma unroll
            for (int k = 0; k < 4; k++) {
                ULL t = st1[idx[k]];
                acc[k][0] = ff2(d0, t, acc[k][0]);
                acc[k][1] = ff2(d1, t, acc[k][1]);
                acc[k][2] = ff2(d2, t, acc[k][2]);
                acc[k][3] = ff2(d3, t, acc[k][3]);
                idx[k] = (idx[k] + kyv[k]) & 255;
            }
        }
        __syncthreads();   // compute done before next store overwrites buffer
    }

    ULL* sRes = reinterpret_cast<ULL*>(buf);
    ULL s2 = pack2(1.f / 256.f, 1.f / 256.f);
    #pragma unroll
    for (int k = 0; k < 4; k++)
        #pragma unroll
        for (int j = 0; j < 4; j++)
            sRes[(lane + 32 * j) * 33 + kyv[k]] = mul2(acc[k][j], s2);
    __syncthreads();
    ULL* Ao = reinterpret_cast<ULL*>(&g_A[(size_t)bc * 8192 + (size_t)h0 * 32]);
    for (int i = tid; i < 4096; i += 256)
        Ao[i] = sRes[(i >> 5) * 33 + (i & 31)];
}

// K2: fwd H, quad fold (unchanged from R16).
__global__ __launch_bounds__(256) void k_fwdH() {
    __shared__ ULL sGP[63 * 32], sKP[63 * 32], sGQ[63 * 32], sKQ[63 * 32];
    __shared__ ULL sD0[64], sD64[64];
    __shared__ ulonglong2 st2[256];
    int bc = blockIdx.x, tid = threadIdx.x;
    const float2* A = &g_A[(size_t)bc * 8192];
    if (tid < 256) st2[tid] = g_t2[tid];
    for (int i = tid; i < 2016; i += 256) {
        int ky = i & 31, h = (i >> 5) + 1;
        float2 a1 = A[h * 32 + ky],         a2 = A[(h + 128) * 32 + ky];
        float2 a3 = A[(128 - h) * 32 + ky], a4 = A[(256 - h) * 32 + ky];
        float Px = a1.x + a2.x, Py = a1.y + a2.y, Qx = a1.x - a2.x, Qy = a1.y - a2.y;
        float Rx = a3.x + a4.x, Ry = a3.y + a4.y, Sx = a3.x - a4.x, Sy = a3.y - a4.y;
        sGP[i] = pack2(Px + Rx, Py + Ry);
        sKP[i] = pack2(Py - Ry, Px - Rx);
        sGQ[i] = pack2(Qx - Sx, Qy - Sy);
        sKQ[i] = pack2(Qy + Sy, Qx + Sx);
    }
    if (tid < 64) {
        int pr = tid >> 5, ky = tid & 31;
        float2 a0 = A[ky], a128 = A[128 * 32 + ky];
        float2 a64 = A[64 * 32 + ky], a192 = A[192 * 32 + ky];
        sD0[tid]  = pr ? pack2(a0.x - a128.x, a0.y - a128.y)
                       : pack2(a0.x + a128.x, a0.y + a128.y);
        sD64[tid] = pr ? pack2(a64.x - a192.x, a64.y - a192.y)
                       : pack2(a64.x + a192.x, a64.y + a192.y);
    }
    __syncthreads();
    int lane = tid & 31, wrp = tid >> 5;
    int par = wrp & 1, base = par + 8 * (wrp >> 1);
    const ULL* sG = par ? sGQ : sGP;
    const ULL* sK = par ? sKQ : sKP;
    float2 d0 = unpack2(sD0[par * 32 + lane]);
    float2 d64 = unpack2(sD64[par * 32 + lane]);
    ULL acc[4]; int idx[4], kxv[4];
    #pragma unroll
    for (int t = 0; t < 4; t++) {
        kxv[t] = base + 2 * t;
        float sg = ((kxv[t] >> 1) & 1) ? -1.f : 1.f;
        acc[t] = par ? pack2(d0.x + sg * d64.y, d0.y - sg * d64.x)
                     : pack2(d0.x + sg * d64.x, d0.y + sg * d64.y);
        idx[t] = kxv[t];
    }
    #pragma unroll 7
    for (int h = 1; h < 64; h++) {
        ULL G = sG[(h - 1) * 32 + lane];
        ULL K = sK[(h - 1) * 32 + lane];
        #pragma unroll
        for (int t = 0; t < 4; t++) {
            ulonglong2 tw = st2[idx[t]];
            acc[t] = ff2(G, tw.x, ff2(K, tw.y, acc[t]));
            idx[t] = (idx[t] + kxv[t]) & 255;
        }
    }
    int b = bc >> 6, c = bc & 63;
    #pragma unroll
    for (int t = 0; t < 4; t++)
        g_X[((size_t)b * 1024 + kxv[t] * 32 + lane) * 64 + c] = unpack2(acc[t]);
}

// K3: channel mix (unchanged).
__global__ __launch_bounds__(256) void k_mix() {
    int m = blockIdx.x;
    __shared__ float2 Ws[4096], Xs[1024];
    for (int i = threadIdx.x; i < 4096; i += 256)
        Ws[i] = g_Wt[(size_t)m * 4096 + i];
    for (int i = threadIdx.x; i < 1024; i += 256)
        Xs[i] = g_X[((size_t)(i >> 6) * 1024 + m) * 64 + (i & 63)];
    __syncthreads();
    #pragma unroll
    for (int k = 0; k < 4; k++) {
        int id = threadIdx.x + k * 256, b = id >> 6, o = id & 63;
        float ar = 0.f, ai = 0.f;
        #pragma unroll 8
        for (int c = 0; c < 64; c++) {
            float2 X = Xs[b * 64 + c], W = Ws[c * 64 + o];
            ar = fmaf(X.x, W.x, fmaf(-X.y, W.y, ar));
            ai = fmaf(X.x, W.y, fmaf( X.y, W.x, ai));
        }
        g_M[((size_t)b * 64 + o) * 1024 + m] = make_float2(ar, ai);
    }
}

// K4: inv H, kx-parity + shared-product fold (unchanged from R16).
__global__ __launch_bounds__(256) void k_invH() {
    __shared__ ULL Ms[1024];
    __shared__ ulonglong2 st4[256];
    int bo = blockIdx.x, tid = threadIdx.x;
    const ULL* M = reinterpret_cast<const ULL*>(&g_M[(size_t)bo * 1024]);
    if (tid < 256) st4[tid] = g_t4[tid];
    for (int i = tid; i < 1024; i += 256) Ms[i] = M[i];
    __syncthreads();
    int lane = tid & 31, wrp = tid >> 5, hb = wrp * 8;
    ULL P1e[8] = {}, P2e[8] = {}, P1o[8] = {}, P2o[8] = {};
    int idx[8];
    #pragma unroll
    for (int j = 0; j < 8; j++) idx[j] = 0;
    #pragma unroll 4
    for (int kx = 0; kx < 32; kx += 2) {
        float2 f = unpack2(Ms[kx * 32 + lane]);
        ULL mrr = pack2(f.x, f.x), mii = pack2(f.y, f.y);
        #pragma unroll
        for (int j = 0; j < 8; j++) {
            ulonglong2 tw = st4[idx[j]];
            P1e[j] = ff2(mrr, tw.x, P1e[j]);
            P2e[j] = ff2(mii, tw.y, P2e[j]);
            idx[j] = (idx[j] + hb + j) & 255;
        }
        float2 g = unpack2(Ms[(kx + 1) * 32 + lane]);
        ULL nrr = pack2(g.x, g.x), nii = pack2(g.y, g.y);
        #pragma unroll
        for (int j = 0; j < 8; j++) {
            ulonglong2 tw = st4[idx[j]];
            P1o[j] = ff2(nrr, tw.x, P1o[j]);
            P2o[j] = ff2(nii, tw.y, P2o[j]);
            idx[j] = (idx[j] + hb + j) & 255;
        }
    }
    float s = (lane == 0 ? 1.f : 2.f) / 256.f;
    float2* T = &g_T[(size_t)bo * 8192];
    #pragma unroll
    for (int j = 0; j < 8; j++) {
        int h = hb + j;
        float2 e1 = unpack2(P1e[j]), e2 = unpack2(P2e[j]);
        float2 o1 = unpack2(P1o[j]), o2 = unpack2(P2o[j]);
        float Aex = e1.x - e2.x, Aey = e1.y + e2.y;
        float Bex = e1.x + e2.x, Bey = e2.y - e1.y;
        float Aox = o1.x - o2.x, Aoy = o1.y + o2.y;
        float Box = o1.x + o2.x, Boy = o2.y - o1.y;
        T[h * 32 + lane]                 = make_float2(s * (Aex + Aox), s * (Aey + Aoy));
        T[(h + 128) * 32 + lane]         = make_float2(s * (Aex - Aox), s * (Aey - Aoy));
        T[((128 - h) & 255) * 32 + lane] = make_float2(s * (Bex - Box), s * (Bey - Boy));
        T[((256 - h) & 255) * 32 + lane] = make_float2(s * (Bex + Box), s * (Bey + Boy));
    }
    if (wrp == 0) {
        float S0x = 0.f, S0y = 0.f, S1x = 0.f, S1y = 0.f;
        for (int kx = 0; kx < 32; kx++) {
            float2 f = unpack2(Ms[kx * 32 + lane]);
            int r = kx & 3;
            if (r == 0)      { S0x += f.x; S0y += f.y; }
            else if (r == 1) { S1x -= f.y; S1y += f.x; }
            else if (r == 2) { S0x -= f.x; S0y -= f.y; }
            else             { S1x += f.y; S1y -= f.x; }
        }
        T[64 * 32 + lane]  = make_float2(s * (S0x + S1x), s * (S0y + S1y));
        T[192 * 32 + lane] = make_float2(s * (S0x - S1x), s * (S0y - S1y));
    }
}

// K5: inverse W via mma.sync bf16 2-split (unchanged from R14).
__global__ __launch_bounds__(256) void k_invW(float* __restrict__ out) {
    __shared__ uint32_t As[2][64][32];
    __shared__ uint32_t Bs[2][128][32];
    int bog = blockIdx.x, w0 = blockIdx.y * 128, h0 = blockIdx.z * 64;
    int tid = threadIdx.x;
    for (int i = tid; i < 4096; i += 256) {
        int w = i >> 5, cb = i & 31;
        int sc = cb ^ ((w & 7) << 2);
        Bs[0][w][sc] = *reinterpret_cast<const uint32_t*>(&g_B5h[(w0 + w) * 64 + cb * 2]);
        Bs[1][w][sc] = *reinterpret_cast<const uint32_t*>(&g_B5l[(w0 + w) * 64 + cb * 2]);
    }
    int lane = tid & 31, wrp = tid >> 5;
    int gid = lane >> 2, tig = lane & 3;
    int wm = wrp & 1, wn = wrp >> 1;
    for (int s = 0; s < 4; s++) {
        int bo = bog * 4 + s;
        __syncthreads();
        const float2* T = &g_T[((size_t)bo * 256 + h0) * 32];
        __nv_bfloat16* Ab = reinterpret_cast<__nv_bfloat16*>(As);
        for (int i = tid; i < 2048; i += 256) {
            int h = i >> 5, ky = i & 31;
            float2 v = T[i];
            #pragma unroll
            for (int q = 0; q < 2; q++) {
                int k = ky + q * 32;
                float f = q ? v.y : v.x;
                __nv_bfloat16 hi = __float2bfloat16(f);
                __nv_bfloat16 lo = __float2bfloat16(f - __bfloat162float(hi));
                int wd = (k >> 1) ^ ((h & 7) << 2);
                int base = (h * 32 + wd) * 2 + (k & 1);
                Ab[base] = hi;
                Ab[4096 + base] = lo;
            }
        }
        __syncthreads();
        float d[2][4][4];
        #pragma unroll
        for (int mt = 0; mt < 2; mt++)
            #pragma unroll
            for (int nt = 0; nt < 4; nt++)
                { d[mt][nt][0]=0.f; d[mt][nt][1]=0.f; d[mt][nt][2]=0.f; d[mt][nt][3]=0.f; }
        #pragma unroll
        for (int c = 0; c < 12; c++) {
            int asel = (c >= 8) ? 1 : 0;
            int bsel = (c >= 4 && c < 8) ? 1 : 0;
            int kb = (c & 3) * 8;
            uint32_t a[2][4];
            #pragma unroll
            for (int mt = 0; mt < 2; mt++) {
                int r0 = wm * 32 + mt * 16 + gid, r1 = r0 + 8;
                a[mt][0] = As[asel][r0][(kb + tig)     ^ ((r0 & 7) << 2)];
                a[mt][1] = As[asel][r1][(kb + tig)     ^ ((r1 & 7) << 2)];
                a[mt][2] = As[asel][r0][(kb + 4 + tig) ^ ((r0 & 7) << 2)];
                a[mt][3] = As[asel][r1][(kb + 4 + tig) ^ ((r1 & 7) << 2)];
            }
            #pragma unroll
            for (int nt = 0; nt < 4; nt++) {
                int wr_ = wn * 32 + nt * 8 + gid;
                uint32_t b0 = Bs[bsel][wr_][(kb + tig)     ^ ((wr_ & 7) << 2)];
                uint32_t b1 = Bs[bsel][wr_][(kb + 4 + tig) ^ ((wr_ & 7) << 2)];
                #pragma unroll
                for (int mt = 0; mt < 2; mt++)
                    mma_bf16(d[mt][nt], a[mt][0], a[mt][1], a[mt][2], a[mt][3], b0, b1);
            }
        }
        float* op = out + (size_t)bo * 65536 + (size_t)h0 * 256 + w0;
        #pragma unroll
        for (int mt = 0; mt < 2; mt++) {
            int r0 = wm * 32 + mt * 16 + gid;
            #pragma unroll
            for (int nt = 0; nt < 4; nt++) {
                int cc = wn * 32 + nt * 8 + tig * 2;
                *reinterpret_cast<float2*>(op + (size_t)r0 * 256 + cc) =
                    make_float2(d[mt][nt][0], d[mt][nt][1]);
                *reinterpret_cast<float2*>(op + (size_t)(r0 + 8) * 256 + cc) =
                    make_float2(d[mt][nt][2], d[mt][nt][3]);
            }
        }
    }
}

extern "C" void kernel_launch(void* const* d_in, const int* in_sizes, int n_in,
                              void* d_out, int out_size) {
    (void)in_sizes; (void)n_in; (void)out_size;
    const float* x  = (const float*)d_in[0];
    const float* wr = (const float*)d_in[1];
    const float* wi = (const float*)d_in[2];
    float* out = (float*)d_out;

    k_tw  <<<1, 256>>>();
    k_tw2 <<<256, 64>>>();
    k_wt  <<<dim3(128, 32), 256>>>(wr, wi);
    k_fwdW<<<dim3(1024, 2), 256>>>(x);
    k_fwdH<<<1024, 256>>>();
    k_mix <<<1024, 256>>>();
    k_invH<<<1024, 256>>>();
    k_invW<<<dim3(256, 2, 4), 256>>>(out);
}